// round 16
// baseline (speedup 1.0000x reference)
#include <cuda_runtime.h>
#include <cstdint>

// Problem constants
constexpr int B_  = 32;
constexpr int T_  = 1024;
constexpr int F_  = 512;
constexpr int H_  = 512;
constexpr int G4H = 2048;   // 4*H

// Recurrence: 4 independent batch groups x 32 blocks.
#define NB 128
#define NT 256
#define NG 4     // groups
#define BG 8     // batch per group
#define HC 16    // h-cols per block

// ---------------- device scratch ----------------
__device__ float g_z0t[(size_t)T_ * B_ * G4H];     // [t][b][gatecol]  (coalesced writes)
__device__ float g_gh[NG][2][H_ * BG];             // per-group h ping-pong [k][b]
// Store-slot barrier: one 128B line per group, one u32 slot per block.
__device__ __align__(128) unsigned g_slots[NG][32];

// ---------------- f32x2 + sync helpers ----------------
__device__ __forceinline__ unsigned long long pack2(float x, float y) {
    unsigned long long r;
    asm("mov.b64 %0, {%1, %2};" : "=l"(r) : "f"(x), "f"(y));
    return r;
}
__device__ __forceinline__ unsigned long long fma2(unsigned long long a,
                                                   unsigned long long b,
                                                   unsigned long long c) {
    unsigned long long d;
    asm("fma.rn.f32x2 %0, %1, %2, %3;" : "=l"(d) : "l"(a), "l"(b), "l"(c));
    return d;
}
__device__ __forceinline__ unsigned long long add2(unsigned long long a,
                                                   unsigned long long b) {
    unsigned long long d;
    asm("add.rn.f32x2 %0, %1, %2;" : "=l"(d) : "l"(a), "l"(b));
    return d;
}
__device__ __forceinline__ float2 unpack2(unsigned long long v) {
    float2 f;
    asm("mov.b64 {%0, %1}, %2;" : "=f"(f.x), "=f"(f.y) : "l"(v));
    return f;
}
__device__ __forceinline__ unsigned ld_acq(const unsigned* p) {
    unsigned v;
    asm volatile("ld.acquire.gpu.global.u32 %0, [%1];"
                 : "=r"(v) : "l"(p) : "memory");
    return v;
}
__device__ __forceinline__ void st_rel(unsigned* p, unsigned v) {
    asm volatile("st.release.gpu.global.u32 [%0], %1;"
                 :: "l"(p), "r"(v) : "memory");
}
__device__ __forceinline__ float sigf(float x) {
    return 1.f / (1.f + __expf(-x));
}
__device__ __forceinline__ float tanh_fast(float x) {
    return 2.f / (1.f + __expf(-2.f * x)) - 1.f;
}

// ---------------- GEMM: 128x64 block tile, 8x4 micro-tile (R15, validated) ----------------
__global__ void __launch_bounds__(256, 2) gemm_xwi(const float* __restrict__ x,
                                                   const float* __restrict__ Wi,
                                                   const float* __restrict__ bias,
                                                   const float* __restrict__ h0) {
    __shared__ float As[2][16][128];   // [buf][k][row]
    __shared__ float Bs[2][16][64];    // [buf][k][col]
    const int tid = threadIdx.x;

    if (blockIdx.x == 0 && blockIdx.y == 0) {
        for (int i = tid; i < NG * H_ * BG; i += 256) {
            int g   = i >> 12;
            int rem = i & 4095;
            int k   = rem >> 3;
            int b   = rem & 7;
            g_gh[g][0][rem] = h0[(size_t)(g * BG + b) * H_ + k];
        }
        if (tid < NG * 32) g_slots[tid >> 5][tid & 31] = 0;
    }

    const int tm = tid >> 4;            // 0..15 -> rows tm*8..+8
    const int tn = tid & 15;            // cols tn*4
    const int row0 = blockIdx.y * 128;
    const int col0 = blockIdx.x * 64;

    unsigned long long acc[8][2] = {};

    const int ar  = tid >> 1;           // 0..127
    const int akq = (tid & 1) * 8;      // 0 or 8
    const int br  = tid >> 4;
    const int bnq = (tid & 15) * 4;

    const float* xp = &x[(size_t)(row0 + ar) * F_ + akq];
    const float* wp = &Wi[(size_t)br * G4H + col0 + bnq];

    float4 av0 = *(const float4*)xp;
    float4 av1 = *(const float4*)(xp + 4);
    float4 bv  = *(const float4*)wp;

    for (int kt = 0; kt < 32; kt++) {
        const int cur = kt & 1;
        As[cur][akq + 0][ar] = av0.x;
        As[cur][akq + 1][ar] = av0.y;
        As[cur][akq + 2][ar] = av0.z;
        As[cur][akq + 3][ar] = av0.w;
        As[cur][akq + 4][ar] = av1.x;
        As[cur][akq + 5][ar] = av1.y;
        As[cur][akq + 6][ar] = av1.z;
        As[cur][akq + 7][ar] = av1.w;
        *(float4*)&Bs[cur][br][bnq] = bv;
        __syncthreads();
        if (kt < 31) {
            av0 = *(const float4*)(xp + (kt + 1) * 16);
            av1 = *(const float4*)(xp + (kt + 1) * 16 + 4);
            bv  = *(const float4*)(wp + (size_t)(kt + 1) * 16 * G4H);
        }
#pragma unroll
        for (int k = 0; k < 16; k++) {
            float4 alo = *(const float4*)&As[cur][k][tm * 8];
            float4 ahi = *(const float4*)&As[cur][k][tm * 8 + 4];
            const unsigned long long* bp =
                (const unsigned long long*)&Bs[cur][k][tn * 4];
            unsigned long long b0 = bp[0], b1 = bp[1];
            unsigned long long p0 = pack2(alo.x, alo.x);
            unsigned long long p1 = pack2(alo.y, alo.y);
            unsigned long long p2 = pack2(alo.z, alo.z);
            unsigned long long p3 = pack2(alo.w, alo.w);
            unsigned long long p4 = pack2(ahi.x, ahi.x);
            unsigned long long p5 = pack2(ahi.y, ahi.y);
            unsigned long long p6 = pack2(ahi.z, ahi.z);
            unsigned long long p7 = pack2(ahi.w, ahi.w);
            acc[0][0] = fma2(p0, b0, acc[0][0]); acc[0][1] = fma2(p0, b1, acc[0][1]);
            acc[1][0] = fma2(p1, b0, acc[1][0]); acc[1][1] = fma2(p1, b1, acc[1][1]);
            acc[2][0] = fma2(p2, b0, acc[2][0]); acc[2][1] = fma2(p2, b1, acc[2][1]);
            acc[3][0] = fma2(p3, b0, acc[3][0]); acc[3][1] = fma2(p3, b1, acc[3][1]);
            acc[4][0] = fma2(p4, b0, acc[4][0]); acc[4][1] = fma2(p4, b1, acc[4][1]);
            acc[5][0] = fma2(p5, b0, acc[5][0]); acc[5][1] = fma2(p5, b1, acc[5][1]);
            acc[6][0] = fma2(p6, b0, acc[6][0]); acc[6][1] = fma2(p6, b1, acc[6][1]);
            acc[7][0] = fma2(p7, b0, acc[7][0]); acc[7][1] = fma2(p7, b1, acc[7][1]);
        }
        __syncthreads();
    }

#pragma unroll
    for (int i = 0; i < 8; i++) {
        int r  = row0 + tm * 8 + i;
        int t  = r & (T_ - 1);
        int bb = r >> 10;
#pragma unroll
        for (int j = 0; j < 2; j++) {
            float2 v = unpack2(acc[i][j]);
            int c0c = col0 + tn * 4 + j * 2;
            float2 o;
            o.x = v.x + bias[c0c + 0];
            o.y = v.y + bias[c0c + 1];
            *(float2*)&g_z0t[((size_t)t * B_ + bb) * G4H + c0c] = o;
        }
    }
}

// ---------------- recurrence: 4 groups; per-warp SLICE dataflow ----------------
// Warp ks consumes only h-slice [64ks,64ks+64), produced by blocks 4ks..4ks+3.
// Each warp polls just those 4 slots and starts its stage+compute immediately.
// red reuse protected by two-phase epilogue: sync(A) -> gather to regs -> sync(B).
// Ring-2 on g_gh safe: a block publishes h(t+2) only after staging ALL slices
// of h(t+1), which implies all 32 producers finished reading h(t).
__global__ void __launch_bounds__(NT, 1) lstm_rec(const float* __restrict__ c0,
                                                  const float* __restrict__ Wh,
                                                  float* __restrict__ out) {
    extern __shared__ unsigned char dsm[];
    unsigned long long* Wsu  = (unsigned long long*)dsm;           // [k*32+hc*2+pr]
    unsigned long long* hdup = Wsu + 512 * 32;                     // [k*8+b] (h,h)
    unsigned long long* red  = hdup + 512 * 8;                     // [ks*256+b*32+lane]
    float* hout = (float*)(red + 8 * 256);                         // [b*16+hc]

    const int tid  = threadIdx.x;
    const int ks   = tid >> 5;                 // warp = k-split / consumed slice
    const int lane = tid & 31;
    const int g    = blockIdx.x & 3;           // group
    const int j    = blockIdx.x >> 2;          // block within group (0..31)

    // Stage this block's Wh slice ONCE: 512 k x 16 hcols x (if),(go) pairs.
    for (int idx = tid; idx < 512 * HC; idx += NT) {
        int k  = idx >> 4;
        int hc = idx & 15;
        int cb = j * HC + hc;
        const float* wr = &Wh[(size_t)k * G4H + cb];
        Wsu[k * 32 + hc * 2 + 0] = pack2(wr[0 * H_], wr[1 * H_]);
        Wsu[k * 32 + hc * 2 + 1] = pack2(wr[2 * H_], wr[3 * H_]);
    }

    // Epilogue-mapped state (tid < 128): b = tid>>4 (0..7), hc = tid&15.
    const int eb = tid >> 4;
    const int ec = tid & 15;
    const int hg = j * HC + ec;                // global h column
    const int bg = g * BG + eb;                // global batch index
    float c = (tid < 128) ? c0[(size_t)bg * H_ + hg] : 0.f;

    float* c_fin = out;
    float* h_fin = out + B_ * H_;
    float* hist  = out + 2 * B_ * H_;          // [b][t][h]

    unsigned* slots = g_slots[g];

    __syncthreads();

    // z prefetch for t = 0 ([t][b][gatecol] layout).
    float z0 = 0.f, z1 = 0.f, z2 = 0.f, z3 = 0.f;
    if (tid < 128) {
        size_t zb = ((size_t)0 * B_ + bg) * G4H + hg;
        z0 = __ldcs(&g_z0t[zb + 0 * H_]);
        z1 = __ldcs(&g_z0t[zb + 1 * H_]);
        z2 = __ldcs(&g_z0t[zb + 2 * H_]);
        z3 = __ldcs(&g_z0t[zb + 3 * H_]);
    }

    for (int t = 0; t < T_; t++) {
        const float4* __restrict__ src4 = (const float4*)g_gh[g][t & 1];
        float* hdst = g_gh[g][(t + 1) & 1];

        // ---- per-warp slice wait: only the 4 producers of slice ks ----
        if (t > 0) {
            const unsigned target = (unsigned)t;
            bool ready;
            do {
                unsigned v = (lane < 4) ? ld_acq(&slots[ks * 4 + lane]) : target;
                ready = __all_sync(0xffffffffu, v >= target);
            } while (!ready);
        }

        // ---- per-warp stage of OWN k-slice: 2KB -> duplicated (h,h) pairs ----
#pragma unroll
        for (int q = 0; q < 4; q++) {
            int i = 128 * ks + lane + 32 * q;
            float4 v = __ldcg(&src4[i]);
            ulonglong2* d = (ulonglong2*)(hdup + 4 * i);
            d[0] = make_ulonglong2(pack2(v.x, v.x), pack2(v.y, v.y));
            d[1] = make_ulonglong2(pack2(v.z, v.z), pack2(v.w, v.w));
        }
        __syncwarp();

        // ---- compute: 64 k; per k: 1 w-load, 4 broadcast h-loads, 8 FFMA2 ----
        unsigned long long a0 = 0, a1 = 0, a2 = 0, a3 = 0;
        unsigned long long a4 = 0, a5 = 0, a6 = 0, a7 = 0;
        {
            const unsigned long long* wq = Wsu + lane;
            const int k0 = 64 * ks;
#pragma unroll 4
            for (int kk = k0; kk < k0 + 64; kk++) {
                unsigned long long wv = wq[kk * 32];
                const ulonglong2* hq = (const ulonglong2*)(hdup + kk * 8);
                ulonglong2 h01 = hq[0];
                ulonglong2 h23 = hq[1];
                ulonglong2 h45 = hq[2];
                ulonglong2 h67 = hq[3];
                a0 = fma2(h01.x, wv, a0); a1 = fma2(h01.y, wv, a1);
                a2 = fma2(h23.x, wv, a2); a3 = fma2(h23.y, wv, a3);
                a4 = fma2(h45.x, wv, a4); a5 = fma2(h45.y, wv, a5);
                a6 = fma2(h67.x, wv, a6); a7 = fma2(h67.y, wv, a7);
            }
        }

        // ---- publish split-k partials: red[ks][b][lane] ----
        red[ks * 256 + 0 * 32 + lane] = a0;
        red[ks * 256 + 1 * 32 + lane] = a1;
        red[ks * 256 + 2 * 32 + lane] = a2;
        red[ks * 256 + 3 * 32 + lane] = a3;
        red[ks * 256 + 4 * 32 + lane] = a4;
        red[ks * 256 + 5 * 32 + lane] = a5;
        red[ks * 256 + 6 * 32 + lane] = a6;
        red[ks * 256 + 7 * 32 + lane] = a7;
        __syncthreads();                        // (A) red published

        // ---- epilogue phase 1: gather partials into registers ----
        unsigned long long aif = 0, ago = 0;
        if (tid < 128) {
            const ulonglong2* rp =
                (const ulonglong2*)(red + eb * 32 + ec * 2);
            aif = pack2(z0, z1);
            ago = pack2(z2, z3);
#pragma unroll
            for (int kq = 0; kq < 8; kq++) {
                ulonglong2 v = rp[kq * 128];   // red + kq*256 (u64) offset
                aif = add2(aif, v.x);
                ago = add2(ago, v.y);
            }
        }
        __syncthreads();                        // (B) red free; warps may run ahead

        // ---- epilogue phase 2: gates + publish + arrive ----
        float h = 0.f;
        if (tid < 128) {
            float2 zif = unpack2(aif);
            float2 zgo = unpack2(ago);

            float ig = sigf(zif.x);
            float fg = sigf(zif.y);
            float gg = tanh_fast(zgo.x);
            float og = sigf(zgo.y);
            c = fg * c + ig * gg;
            h = og * tanh_fast(c);

            __stcg(&hdst[hg * BG + eb], h);    // publish to group h(t+1)
            hout[eb * HC + ec] = h;

            // epilogue-only sync: publishes complete before the release-store.
            asm volatile("bar.sync 1, 128;" ::: "memory");

            // ---- arrive: plain release store to OWN slot (no atomic) ----
            if (tid == 0) st_rel(&slots[j], (unsigned)(t + 1));
        }

        // ---- off-critical-path tail: hist + next z prefetch + finals ----
        if (tid < 32) {
            int bq = tid >> 2;                 // local b
            int qq = tid & 3;                  // float4 quarter
            float4 hv4 = *(const float4*)&hout[bq * HC + qq * 4];
            *(float4*)&hist[((size_t)(g * BG + bq) * T_ + t) * H_
                            + j * HC + qq * 4] = hv4;
        }
        if (tid < 128) {
            if (t == T_ - 1) {
                c_fin[(size_t)bg * H_ + hg] = c;
                h_fin[(size_t)bg * H_ + hg] = h;
            } else {
                size_t zb = ((size_t)(t + 1) * B_ + bg) * G4H + hg;
                z0 = __ldcs(&g_z0t[zb + 0 * H_]);
                z1 = __ldcs(&g_z0t[zb + 1 * H_]);
                z2 = __ldcs(&g_z0t[zb + 2 * H_]);
                z3 = __ldcs(&g_z0t[zb + 3 * H_]);
            }
        }
    }
}

// ---------------- launch ----------------
extern "C" void kernel_launch(void* const* d_in, const int* in_sizes, int n_in,
                              void* d_out, int out_size) {
    const float* x    = (const float*)d_in[0];
    const float* h0   = (const float*)d_in[1];
    const float* c0   = (const float*)d_in[2];
    const float* Wi   = (const float*)d_in[3];
    const float* Wh   = (const float*)d_in[4];
    const float* bias = (const float*)d_in[5];
    float* out = (float*)d_out;

    // 128KB (Wsu) + 32KB (hdup) + 16KB (red) + 512B (hout) = 180736 B
    const int rec_smem = 512 * 32 * 8 + 512 * 8 * 8 + 8 * 256 * 8 + 128 * 4;
    cudaFuncSetAttribute(lstm_rec, cudaFuncAttributeMaxDynamicSharedMemorySize,
                         rec_smem);

    dim3 ggrid(G4H / 64, (B_ * T_) / 128);
    gemm_xwi<<<ggrid, 256>>>(x, Wi, bias, h0);

    lstm_rec<<<NB, NT, rec_smem>>>(c0, Wh, out);
}